// round 12
// baseline (speedup 1.0000x reference)
#include <cuda_runtime.h>
#include <cuda_fp16.h>
#include <stdint.h>

#define NB 4096
#define ND 256
#define NM 60
#define TILE 128
#define NT (NB / TILE)              // 32
#define NPAIR (NT * (NT + 1) / 2)   // 528
#define RSTRIDE 40                  // smem row stride in words (8 mod 32 => LDS.64 conflict-free)

// Device scratch (allocation-free). uint4-typed => 16B alignment.
__device__ uint4    g_norm4[NB * ND * 2 / 16]; // fp16 normalized reps [NB][ND]
__device__ uint4    g_mask[NB];
__device__ int      g_cnt[NB];
__device__ float4   g_part4[NPAIR];
__device__ unsigned g_ctr;                     // zero-init; reset by last block

// ---------------------------------------------------------------------------
// Prep (UNCHANGED from R7/R11, proven 6us): warp-per-row normalize + mask.
// ---------------------------------------------------------------------------
__global__ void __launch_bounds__(256) k_prep(const float* __restrict__ rep,
                                              const long long* __restrict__ codes) {
    int w    = threadIdx.x >> 5;
    int lane = threadIdx.x & 31;
    int row  = blockIdx.x * 8 + w;
    if (blockIdx.x == 0 && threadIdx.x == 0) g_ctr = 0u;   // guard reset

    const float4* rp = reinterpret_cast<const float4*>(rep + (size_t)row * ND);
    float4 x0 = rp[lane * 2];
    float4 x1 = rp[lane * 2 + 1];
    float ss = x0.x * x0.x + x0.y * x0.y + x0.z * x0.z + x0.w * x0.w
             + x1.x * x1.x + x1.y * x1.y + x1.z * x1.z + x1.w * x1.w;
    #pragma unroll
    for (int o = 16; o; o >>= 1) ss += __shfl_xor_sync(0xffffffffu, ss, o);
    float inv = rsqrtf(ss);

    __half2 h[4];
    h[0] = __floats2half2_rn(x0.x * inv, x0.y * inv);
    h[1] = __floats2half2_rn(x0.z * inv, x0.w * inv);
    h[2] = __floats2half2_rn(x1.x * inv, x1.y * inv);
    h[3] = __floats2half2_rn(x1.z * inv, x1.w * inv);
    g_norm4[(size_t)row * 32 + lane] = *reinterpret_cast<uint4*>(h);

    const long long* mc = codes + (size_t)row * NM;
    uint32_t m0 = 0, m1 = 0, m2 = 0, m3 = 0;
    {
        int c = (int)mc[lane];
        uint32_t b = 1u << (c & 31);
        int wd = c >> 5;
        if      (wd == 0) m0 |= b;
        else if (wd == 1) m1 |= b;
        else if (wd == 2) m2 |= b;
        else              m3 |= b;
    }
    if (lane < NM - 32) {
        int c = (int)mc[32 + lane];
        uint32_t b = 1u << (c & 31);
        int wd = c >> 5;
        if      (wd == 0) m0 |= b;
        else if (wd == 1) m1 |= b;
        else if (wd == 2) m2 |= b;
        else              m3 |= b;
    }
    #pragma unroll
    for (int o = 16; o; o >>= 1) {
        m0 |= __shfl_xor_sync(0xffffffffu, m0, o);
        m1 |= __shfl_xor_sync(0xffffffffu, m1, o);
        m2 |= __shfl_xor_sync(0xffffffffu, m2, o);
        m3 |= __shfl_xor_sync(0xffffffffu, m3, o);
    }
    if (lane == 0) {
        g_mask[row] = make_uint4(m0, m1, m2, m3);
        g_cnt[row]  = __popc(m0) + __popc(m1) + __popc(m2) + __popc(m3);
    }
}

// ---------------------------------------------------------------------------
// mma (f16 in, f32 acc), explicit A regs. k-permutation note: we feed
// physical word pairs (lo,hi)=(words 2tg, 2tg+1) into MMA k-slots
// (2tg, 2tg+8) for BOTH A and B — a consistent permutation of k, so the
// dot product is bit-identical to the canonical order.
// ---------------------------------------------------------------------------
#define MMA4X(D, A0, A1, A2, A3, B0, B1)                                     \
    asm volatile("mma.sync.aligned.m16n8k16.row.col.f32.f16.f16.f32 "        \
                 "{%0,%1,%2,%3},{%4,%5,%6,%7},{%8,%9},{%0,%1,%2,%3};\n"      \
                 : "+f"((D)[0]), "+f"((D)[1]), "+f"((D)[2]), "+f"((D)[3])    \
                 : "r"(A0), "r"(A1), "r"(A2), "r"(A3), "r"(B0), "r"(B1))

#define PROC(ACC, MA, CA, MB, CB, EQ) do {                                   \
    int inter = __popc((MA).x & (MB).x) + __popc((MA).y & (MB).y) +          \
                __popc((MA).z & (MB).z) + __popc((MA).w & (MB).w);           \
    bool pos = (10 * inter > 3 * ((CA) + (CB) - inter)) && !(EQ);            \
    float s = (ACC) * 10.0f;                                                 \
    float e = __expf(s);                                                     \
    if (pos) { scnt++; sps += s; spe += e; } else { sneg += e; }             \
} while (0)

// ---------------------------------------------------------------------------
// Main pass (R11 structure; LDS.64 fragments + __expf epilogue).
// One block per upper-tri 128x128 tile pair; fused last-block final.
// ---------------------------------------------------------------------------
__global__ void __launch_bounds__(256, 2) k_pair(float* __restrict__ out) {
    __shared__ uint32_t sA[TILE * RSTRIDE];   // 20480 B
    __shared__ uint32_t sB[TILE * RSTRIDE];   // 20480 B
    __shared__ uint4 smMA[TILE], smMB[TILE];
    __shared__ int   scA[TILE], scB[TILE];
    __shared__ float red[32];
    __shared__ double sdd[32];
    __shared__ int   flag;

    int tid = threadIdx.x;

    // decode blockIdx -> (ti, tj), ti <= tj
    int p = blockIdx.x, ti = 0;
    while (p >= NT - ti) { p -= NT - ti; ti++; }
    int tj = ti + p;
    int i0 = ti * TILE, j0 = tj * TILE;
    bool diag = (ti == tj);

    if (tid < TILE) { smMA[tid] = g_mask[i0 + tid]; scA[tid] = g_cnt[i0 + tid]; }
    else { int q = tid - TILE; smMB[q] = g_mask[j0 + q]; scB[q] = g_cnt[j0 + q]; }

    int lane = tid & 31, w = tid >> 5;
    int wm = w & 3, wn = w >> 2;                 // warp grid: 4(M) x 2(N)
    int g = lane >> 2, tg = lane & 3;

    float acc[64];
    #pragma unroll
    for (int i = 0; i < 64; i++) acc[i] = 0.0f;

    // register prefetch buffers: chunk kc's data staged through regs
    uint4 pva[4], pvb[4];
    #pragma unroll
    for (int r = 0; r < 4; r++) {
        int idx = tid + r * 256;
        int row = idx >> 3, seg = idx & 7;
        pva[r] = g_norm4[(size_t)(i0 + row) * 32 + seg];
        pvb[r] = g_norm4[(size_t)(j0 + row) * 32 + seg];
    }

    // K = 256 elems = 4 chunks of 64 elems (8 uint4 per row per chunk)
    #pragma unroll 1
    for (int kc = 0; kc < 4; kc++) {
        __syncthreads();                         // previous compute done (and masks on kc==0)
        #pragma unroll
        for (int r = 0; r < 4; r++) {
            int idx = tid + r * 256;
            int row = idx >> 3, seg = idx & 7;
            *reinterpret_cast<uint4*>(&sA[row * RSTRIDE + seg * 4]) = pva[r];
            *reinterpret_cast<uint4*>(&sB[row * RSTRIDE + seg * 4]) = pvb[r];
        }
        __syncthreads();

        if (kc < 3) {                            // prefetch next chunk (hides LDG latency)
            #pragma unroll
            for (int r = 0; r < 4; r++) {
                int idx = tid + r * 256;
                int row = idx >> 3, seg = idx & 7;
                pva[r] = g_norm4[(size_t)(i0 + row) * 32 + (kc + 1) * 8 + seg];
                pvb[r] = g_norm4[(size_t)(j0 + row) * 32 + (kc + 1) * 8 + seg];
            }
        }

        #pragma unroll
        for (int kk = 0; kk < 4; kk++) {         // 4 k16 slices per chunk
            int ko = kk * 8 + 2 * tg;            // paired 64-bit word offset
            uint2 a0p[2], a1p[2];                // [mi]: rows g / g+8 pairs
            #pragma unroll
            for (int mi = 0; mi < 2; mi++) {
                int rb = (wm * 32 + mi * 16 + g) * RSTRIDE + ko;
                a0p[mi] = *reinterpret_cast<uint2*>(&sA[rb]);
                a1p[mi] = *reinterpret_cast<uint2*>(&sA[rb + 8 * RSTRIDE]);
            }
            #pragma unroll
            for (int nt = 0; nt < 8; nt++) {
                int rb = (wn * 64 + nt * 8 + g) * RSTRIDE + ko;
                uint2 b = *reinterpret_cast<uint2*>(&sB[rb]);
                MMA4X(acc + nt * 4,      a0p[0].x, a1p[0].x, a0p[0].y, a1p[0].y, b.x, b.y);
                MMA4X(acc + 32 + nt * 4, a0p[1].x, a1p[1].x, a0p[1].y, a1p[1].y, b.x, b.y);
            }
        }
    }

    // ---- epilogue (same mapping as R11; __expf replaces poly exp) ----
    float sneg = 0.0f, spe = 0.0f, sps = 0.0f;
    int scnt = 0;

    #pragma unroll
    for (int mi = 0; mi < 2; mi++) {
        int rl0 = wm * 32 + mi * 16 + g;
        uint4 mA0 = smMA[rl0];     int cA0 = scA[rl0];
        uint4 mA1 = smMA[rl0 + 8]; int cA1 = scA[rl0 + 8];
        #pragma unroll
        for (int nt = 0; nt < 8; nt++) {
            int cl = wn * 64 + nt * 8 + tg * 2;
            uint4 mB0 = smMB[cl];     int cB0 = scB[cl];
            uint4 mB1 = smMB[cl + 1]; int cB1 = scB[cl + 1];
            float* A4 = acc + mi * 32 + nt * 4;
            PROC(A4[0], mA0, cA0, mB0, cB0, diag && (rl0 == cl));
            PROC(A4[1], mA0, cA0, mB1, cB1, diag && (rl0 == cl + 1));
            PROC(A4[2], mA1, cA1, mB0, cB0, diag && (rl0 + 8 == cl));
            PROC(A4[3], mA1, cA1, mB1, cB1, diag && (rl0 + 8 == cl + 1));
        }
    }

    // block reduce (deterministic, no atomics in the sums)
    float v0 = sneg, v1 = spe, v2 = sps, v3 = (float)scnt;
    #pragma unroll
    for (int o = 16; o; o >>= 1) {
        v0 += __shfl_xor_sync(0xffffffffu, v0, o);
        v1 += __shfl_xor_sync(0xffffffffu, v1, o);
        v2 += __shfl_xor_sync(0xffffffffu, v2, o);
        v3 += __shfl_xor_sync(0xffffffffu, v3, o);
    }
    if (lane == 0) { red[w * 4 + 0] = v0; red[w * 4 + 1] = v1;
                     red[w * 4 + 2] = v2; red[w * 4 + 3] = v3; }
    __syncthreads();
    if (tid == 0) {
        float n = 0, pe = 0, ps = 0, pc = 0;
        #pragma unroll
        for (int i = 0; i < 8; i++) {
            n += red[i * 4 + 0]; pe += red[i * 4 + 1];
            ps += red[i * 4 + 2]; pc += red[i * 4 + 3];
        }
        float f = diag ? 1.0f : 2.0f;   // off-diag tiles stand for (i,j) and (j,i)
        g_part4[blockIdx.x] = make_float4(n * f, pe * f, ps * f, pc * f);
        __threadfence();                 // publish partial before counting
        unsigned v = atomicAdd(&g_ctr, 1u);
        flag = (v == NPAIR - 1) ? 1 : 0;
    }
    __syncthreads();
    if (!flag) return;

    // ---- last block: deterministic double-precision final reduction ----
    __threadfence();                     // order reads after the atomic
    if (tid == 0) g_ctr = 0u;            // reset for next graph replay
    double n = 0, pe = 0, ps = 0, pc = 0;
    for (int q = tid; q < NPAIR; q += 256) {
        float4 v = __ldcg(&g_part4[q]);
        n += (double)v.x; pe += (double)v.y;
        ps += (double)v.z; pc += (double)v.w;
    }
    #pragma unroll
    for (int o = 16; o; o >>= 1) {
        n  += __shfl_xor_sync(0xffffffffu, n,  o);
        pe += __shfl_xor_sync(0xffffffffu, pe, o);
        ps += __shfl_xor_sync(0xffffffffu, ps, o);
        pc += __shfl_xor_sync(0xffffffffu, pc, o);
    }
    if (lane == 0) { sdd[w * 4 + 0] = n; sdd[w * 4 + 1] = pe;
                     sdd[w * 4 + 2] = ps; sdd[w * 4 + 3] = pc; }
    __syncthreads();
    if (tid == 0) {
        double N = 0, PE = 0, PS = 0, PC = 0;
        #pragma unroll
        for (int i = 0; i < 8; i++) {
            N += sdd[i * 4 + 0]; PE += sdd[i * 4 + 1];
            PS += sdd[i * 4 + 2]; PC += sdd[i * 4 + 3];
        }
        double loss = 0.0;
        if (PC > 0.0) loss = log(N) + PE / (N * PC) - PS / PC;
        out[0] = (float)loss;
    }
}

extern "C" void kernel_launch(void* const* d_in, const int* in_sizes, int n_in,
                              void* d_out, int out_size) {
    (void)in_sizes; (void)n_in; (void)out_size;
    const float*     rep   = (const float*)d_in[0];
    const long long* codes = (const long long*)d_in[1];
    // d_in[2] = labels: unused by the reference loss

    k_prep<<<NB / 8, 256>>>(rep, codes);
    k_pair<<<NPAIR, 256>>>((float*)d_out);
}

// round 13
// speedup vs baseline: 1.4288x; 1.4288x over previous
#include <cuda_runtime.h>
#include <cuda_fp16.h>
#include <stdint.h>

#define NB 4096
#define ND 256
#define NM 60
#define TILE 128
#define NT (NB / TILE)              // 32
#define NPAIR (NT * (NT + 1) / 2)   // 528
#define RSTRIDE 40                  // smem row stride in words (8 mod 32 => LDS.64 conflict-free)

// Device scratch (allocation-free). uint4-typed => 16B alignment.
__device__ uint4    g_norm4[NB * ND * 2 / 16]; // fp16 normalized reps [NB][ND]
__device__ uint4    g_mask[NB];
__device__ int      g_cnt[NB];
__device__ float4   g_part4[NPAIR];
__device__ unsigned g_ctr;                     // zero-init; reset by last block

// ---------------------------------------------------------------------------
// fexp10(a) = exp(10*a), FMA-only. Temperature (x10) and ln2 are folded in:
//   t = a * (10*log2e); split t = round(t) + f; exp(10a) = 2^round * P(f)
//   P(f) = sum ln2^i/i! f^i  (deg 6; rel err ~1.5e-7 over |f|<=0.5)
// ---------------------------------------------------------------------------
__device__ __forceinline__ float fexp10(float a) {
    const float S     = 14.426950408889634f;     // 10 * log2(e)
    const float MAGIC = 12582912.0f;             // 1.5 * 2^23
    float t  = a * S;
    float r  = fmaf(a, S, MAGIC);
    int   ei = __float_as_int(r) - 0x4B400000;
    float f  = t - (r - MAGIC);                  // f in [-0.5, 0.5]
    float p  = fmaf(f, fmaf(f, fmaf(f, fmaf(f, fmaf(f,
                 fmaf(f, 1.5403530e-4f, 1.3333558e-3f),
                 9.6181291e-3f), 5.5504109e-2f), 2.4022651e-1f),
                 6.9314718e-1f), 1.0f);
    return __int_as_float(__float_as_int(p) + (ei << 23));
}

// ---------------------------------------------------------------------------
// Prep (R7/R11 proven; only change: g_cnt stores 3*count for cheap Jaccard).
// ---------------------------------------------------------------------------
__global__ void __launch_bounds__(256) k_prep(const float* __restrict__ rep,
                                              const long long* __restrict__ codes) {
    int w    = threadIdx.x >> 5;
    int lane = threadIdx.x & 31;
    int row  = blockIdx.x * 8 + w;
    if (blockIdx.x == 0 && threadIdx.x == 0) g_ctr = 0u;   // guard reset

    const float4* rp = reinterpret_cast<const float4*>(rep + (size_t)row * ND);
    float4 x0 = rp[lane * 2];
    float4 x1 = rp[lane * 2 + 1];
    float ss = x0.x * x0.x + x0.y * x0.y + x0.z * x0.z + x0.w * x0.w
             + x1.x * x1.x + x1.y * x1.y + x1.z * x1.z + x1.w * x1.w;
    #pragma unroll
    for (int o = 16; o; o >>= 1) ss += __shfl_xor_sync(0xffffffffu, ss, o);
    float inv = rsqrtf(ss);

    __half2 h[4];
    h[0] = __floats2half2_rn(x0.x * inv, x0.y * inv);
    h[1] = __floats2half2_rn(x0.z * inv, x0.w * inv);
    h[2] = __floats2half2_rn(x1.x * inv, x1.y * inv);
    h[3] = __floats2half2_rn(x1.z * inv, x1.w * inv);
    g_norm4[(size_t)row * 32 + lane] = *reinterpret_cast<uint4*>(h);

    const long long* mc = codes + (size_t)row * NM;
    uint32_t m0 = 0, m1 = 0, m2 = 0, m3 = 0;
    {
        int c = (int)mc[lane];
        uint32_t b = 1u << (c & 31);
        int wd = c >> 5;
        if      (wd == 0) m0 |= b;
        else if (wd == 1) m1 |= b;
        else if (wd == 2) m2 |= b;
        else              m3 |= b;
    }
    if (lane < NM - 32) {
        int c = (int)mc[32 + lane];
        uint32_t b = 1u << (c & 31);
        int wd = c >> 5;
        if      (wd == 0) m0 |= b;
        else if (wd == 1) m1 |= b;
        else if (wd == 2) m2 |= b;
        else              m3 |= b;
    }
    #pragma unroll
    for (int o = 16; o; o >>= 1) {
        m0 |= __shfl_xor_sync(0xffffffffu, m0, o);
        m1 |= __shfl_xor_sync(0xffffffffu, m1, o);
        m2 |= __shfl_xor_sync(0xffffffffu, m2, o);
        m3 |= __shfl_xor_sync(0xffffffffu, m3, o);
    }
    if (lane == 0) {
        g_mask[row] = make_uint4(m0, m1, m2, m3);
        g_cnt[row]  = 3 * (__popc(m0) + __popc(m1) + __popc(m2) + __popc(m3));
    }
}

// ---------------------------------------------------------------------------
// mma (f16 in, f32 acc), explicit A regs. Consistent k-permutation of word
// pairs for A and B => dot product bit-identical (proven in R12: same rel_err).
// ---------------------------------------------------------------------------
#define MMA4X(D, A0, A1, A2, A3, B0, B1)                                     \
    asm volatile("mma.sync.aligned.m16n8k16.row.col.f32.f16.f16.f32 "        \
                 "{%0,%1,%2,%3},{%4,%5,%6,%7},{%8,%9},{%0,%1,%2,%3};\n"      \
                 : "+f"((D)[0]), "+f"((D)[1]), "+f"((D)[2]), "+f"((D)[3])    \
                 : "r"(A0), "r"(A1), "r"(A2), "r"(A3), "r"(B0), "r"(B1))

// Jaccard: 10*inter > 3*(cA+cB-inter)  <=>  13*inter > 3cA + 3cB (exact).
// C3A/C3B are the precomputed 3*count values.
#define PROC(ACC, MA, C3A, MB, C3B, EQ) do {                                 \
    int inter = __popc((MA).x & (MB).x) + __popc((MA).y & (MB).y) +          \
                __popc((MA).z & (MB).z) + __popc((MA).w & (MB).w);           \
    bool pos = (13 * inter > (C3A) + (C3B)) && !(EQ);                        \
    float e = fexp10(ACC);                                                   \
    if (pos) { scnt++; sps += (ACC); spe += e; } else { sneg += e; }         \
} while (0)

// ---------------------------------------------------------------------------
// Main pass: one block per upper-tri 128x128 tile pair; LDS.64 fragments;
// register-prefetch staging; fused last-block final reduction.
// ---------------------------------------------------------------------------
__global__ void __launch_bounds__(256, 2) k_pair(float* __restrict__ out) {
    __shared__ uint32_t sA[TILE * RSTRIDE];   // 20480 B
    __shared__ uint32_t sB[TILE * RSTRIDE];   // 20480 B
    __shared__ uint4 smMA[TILE], smMB[TILE];
    __shared__ int   scA[TILE], scB[TILE];    // 3*count
    __shared__ float red[32];
    __shared__ double sdd[32];
    __shared__ int   flag;

    int tid = threadIdx.x;

    // decode blockIdx -> (ti, tj), ti <= tj
    int p = blockIdx.x, ti = 0;
    while (p >= NT - ti) { p -= NT - ti; ti++; }
    int tj = ti + p;
    int i0 = ti * TILE, j0 = tj * TILE;
    bool diag = (ti == tj);

    if (tid < TILE) { smMA[tid] = g_mask[i0 + tid]; scA[tid] = g_cnt[i0 + tid]; }
    else { int q = tid - TILE; smMB[q] = g_mask[j0 + q]; scB[q] = g_cnt[j0 + q]; }

    int lane = tid & 31, w = tid >> 5;
    int wm = w & 3, wn = w >> 2;                 // warp grid: 4(M) x 2(N)
    int g = lane >> 2, tg = lane & 3;

    float acc[64];
    #pragma unroll
    for (int i = 0; i < 64; i++) acc[i] = 0.0f;

    // register prefetch buffers: chunk kc's data staged through regs
    uint4 pva[4], pvb[4];
    #pragma unroll
    for (int r = 0; r < 4; r++) {
        int idx = tid + r * 256;
        int row = idx >> 3, seg = idx & 7;
        pva[r] = g_norm4[(size_t)(i0 + row) * 32 + seg];
        pvb[r] = g_norm4[(size_t)(j0 + row) * 32 + seg];
    }

    // K = 256 elems = 4 chunks of 64 elems (8 uint4 per row per chunk)
    #pragma unroll 1
    for (int kc = 0; kc < 4; kc++) {
        __syncthreads();                         // previous compute done (and masks on kc==0)
        #pragma unroll
        for (int r = 0; r < 4; r++) {
            int idx = tid + r * 256;
            int row = idx >> 3, seg = idx & 7;
            *reinterpret_cast<uint4*>(&sA[row * RSTRIDE + seg * 4]) = pva[r];
            *reinterpret_cast<uint4*>(&sB[row * RSTRIDE + seg * 4]) = pvb[r];
        }
        __syncthreads();

        if (kc < 3) {                            // prefetch next chunk (hides LDG latency)
            #pragma unroll
            for (int r = 0; r < 4; r++) {
                int idx = tid + r * 256;
                int row = idx >> 3, seg = idx & 7;
                pva[r] = g_norm4[(size_t)(i0 + row) * 32 + (kc + 1) * 8 + seg];
                pvb[r] = g_norm4[(size_t)(j0 + row) * 32 + (kc + 1) * 8 + seg];
            }
        }

        #pragma unroll
        for (int kk = 0; kk < 4; kk++) {         // 4 k16 slices per chunk
            int ko = kk * 8 + 2 * tg;            // paired 64-bit word offset
            uint2 a0p[2], a1p[2];                // [mi]: rows g / g+8 pairs
            #pragma unroll
            for (int mi = 0; mi < 2; mi++) {
                int rb = (wm * 32 + mi * 16 + g) * RSTRIDE + ko;
                a0p[mi] = *reinterpret_cast<uint2*>(&sA[rb]);
                a1p[mi] = *reinterpret_cast<uint2*>(&sA[rb + 8 * RSTRIDE]);
            }
            #pragma unroll
            for (int nt = 0; nt < 8; nt++) {
                int rb = (wn * 64 + nt * 8 + g) * RSTRIDE + ko;
                uint2 b = *reinterpret_cast<uint2*>(&sB[rb]);
                MMA4X(acc + nt * 4,      a0p[0].x, a1p[0].x, a0p[0].y, a1p[0].y, b.x, b.y);
                MMA4X(acc + 32 + nt * 4, a0p[1].x, a1p[1].x, a0p[1].y, a1p[1].y, b.x, b.y);
            }
        }
    }

    // ---- epilogue ----
    float sneg = 0.0f, spe = 0.0f, sps = 0.0f;
    int scnt = 0;

    #pragma unroll
    for (int mi = 0; mi < 2; mi++) {
        int rl0 = wm * 32 + mi * 16 + g;
        uint4 mA0 = smMA[rl0];     int cA0 = scA[rl0];
        uint4 mA1 = smMA[rl0 + 8]; int cA1 = scA[rl0 + 8];
        #pragma unroll
        for (int nt = 0; nt < 8; nt++) {
            int cl = wn * 64 + nt * 8 + tg * 2;
            uint4 mB0 = smMB[cl];     int cB0 = scB[cl];
            uint4 mB1 = smMB[cl + 1]; int cB1 = scB[cl + 1];
            float* A4 = acc + mi * 32 + nt * 4;
            PROC(A4[0], mA0, cA0, mB0, cB0, diag && (rl0 == cl));
            PROC(A4[1], mA0, cA0, mB1, cB1, diag && (rl0 == cl + 1));
            PROC(A4[2], mA1, cA1, mB0, cB0, diag && (rl0 + 8 == cl));
            PROC(A4[3], mA1, cA1, mB1, cB1, diag && (rl0 + 8 == cl + 1));
        }
    }

    // block reduce (deterministic, no atomics in the sums)
    float v0 = sneg, v1 = spe, v2 = sps, v3 = (float)scnt;
    #pragma unroll
    for (int o = 16; o; o >>= 1) {
        v0 += __shfl_xor_sync(0xffffffffu, v0, o);
        v1 += __shfl_xor_sync(0xffffffffu, v1, o);
        v2 += __shfl_xor_sync(0xffffffffu, v2, o);
        v3 += __shfl_xor_sync(0xffffffffu, v3, o);
    }
    if (lane == 0) { red[w * 4 + 0] = v0; red[w * 4 + 1] = v1;
                     red[w * 4 + 2] = v2; red[w * 4 + 3] = v3; }
    __syncthreads();
    if (tid == 0) {
        float n = 0, pe = 0, ps = 0, pc = 0;
        #pragma unroll
        for (int i = 0; i < 8; i++) {
            n += red[i * 4 + 0]; pe += red[i * 4 + 1];
            ps += red[i * 4 + 2]; pc += red[i * 4 + 3];
        }
        float f = diag ? 1.0f : 2.0f;   // off-diag tiles stand for (i,j) and (j,i)
        // ps accumulated raw acc values; rescale by temperature (x10) here.
        g_part4[blockIdx.x] = make_float4(n * f, pe * f, ps * 10.0f * f, pc * f);
        __threadfence();                 // publish partial before counting
        unsigned v = atomicAdd(&g_ctr, 1u);
        flag = (v == NPAIR - 1) ? 1 : 0;
    }
    __syncthreads();
    if (!flag) return;

    // ---- last block: deterministic double-precision final reduction ----
    __threadfence();                     // order reads after the atomic
    if (tid == 0) g_ctr = 0u;            // reset for next graph replay
    double n = 0, pe = 0, ps = 0, pc = 0;
    for (int q = tid; q < NPAIR; q += 256) {
        float4 v = __ldcg(&g_part4[q]);
        n += (double)v.x; pe += (double)v.y;
        ps += (double)v.z; pc += (double)v.w;
    }
    #pragma unroll
    for (int o = 16; o; o >>= 1) {
        n  += __shfl_xor_sync(0xffffffffu, n,  o);
        pe += __shfl_xor_sync(0xffffffffu, pe, o);
        ps += __shfl_xor_sync(0xffffffffu, ps, o);
        pc += __shfl_xor_sync(0xffffffffu, pc, o);
    }
    if (lane == 0) { sdd[w * 4 + 0] = n; sdd[w * 4 + 1] = pe;
                     sdd[w * 4 + 2] = ps; sdd[w * 4 + 3] = pc; }
    __syncthreads();
    if (tid == 0) {
        double N = 0, PE = 0, PS = 0, PC = 0;
        #pragma unroll
        for (int i = 0; i < 8; i++) {
            N += sdd[i * 4 + 0]; PE += sdd[i * 4 + 1];
            PS += sdd[i * 4 + 2]; PC += sdd[i * 4 + 3];
        }
        double loss = 0.0;
        if (PC > 0.0) loss = log(N) + PE / (N * PC) - PS / PC;
        out[0] = (float)loss;
    }
}

extern "C" void kernel_launch(void* const* d_in, const int* in_sizes, int n_in,
                              void* d_out, int out_size) {
    (void)in_sizes; (void)n_in; (void)out_size;
    const float*     rep   = (const float*)d_in[0];
    const long long* codes = (const long long*)d_in[1];
    // d_in[2] = labels: unused by the reference loss

    k_prep<<<NB / 8, 256>>>(rep, codes);
    k_pair<<<NPAIR, 256>>>((float*)d_out);
}